// round 11
// baseline (speedup 1.0000x reference)
#include <cuda_runtime.h>
#include <cuda_bf16.h>
#include <cstdint>

#define NEU   64
#define HID   32
#define GD    103
#define N_MAX 2000128
#define B_MAX 8192

typedef unsigned long long ull;

// Scratch
__device__ float        g_logit[N_MAX];
__device__ float        g_G[B_MAX * HID];
__device__ unsigned int g_maxenc[B_MAX];
__device__ float        g_sum[B_MAX];
__device__ int          g_dummy;

__device__ __forceinline__ unsigned int enc_f(float f) {
    unsigned int u = __float_as_uint(f);
    return (u & 0x80000000u) ? ~u : (u | 0x80000000u);
}
__device__ __forceinline__ float dec_f(unsigned int u) {
    u = (u & 0x80000000u) ? (u & 0x7FFFFFFFu) : ~u;
    return __uint_as_float(u);
}

__device__ __forceinline__ uint32_t smem_u32(const void* p) {
    uint32_t a;
    asm("{ .reg .u64 t; cvta.to.shared.u64 t, %1; cvt.u32.u64 %0, t; }"
        : "=r"(a) : "l"(p));
    return a;
}
__device__ __forceinline__ void ldsm_x2(uint32_t r[2], uint32_t addr) {
    asm volatile("ldmatrix.sync.aligned.m8n8.x2.shared.b16 {%0,%1}, [%2];"
        : "=r"(r[0]), "=r"(r[1]) : "r"(addr));
}
__device__ __forceinline__ void mma_bf16(float c[4], const uint32_t a[4],
                                         const uint32_t b[2]) {
    asm volatile(
        "mma.sync.aligned.m16n8k16.row.col.f32.bf16.bf16.f32 "
        "{%0,%1,%2,%3}, {%4,%5,%6,%7}, {%8,%9}, {%0,%1,%2,%3};"
        : "+f"(c[0]), "+f"(c[1]), "+f"(c[2]), "+f"(c[3])
        : "r"(a[0]), "r"(a[1]), "r"(a[2]), "r"(a[3]), "r"(b[0]), "r"(b[1]));
}
__device__ __forceinline__ void cp16(uint32_t dst, const void* src) {
    asm volatile("cp.async.ca.shared.global [%0], [%1], 16;"
                 :: "r"(dst), "l"(src) : "memory");
}
#define CP_COMMIT() asm volatile("cp.async.commit_group;" ::: "memory")
#define CP_WAIT1()  asm volatile("cp.async.wait_group 1;" ::: "memory")

// ---------------------------------------------------------------------------
__global__ void k_init(int b) {
    int i = blockIdx.x * blockDim.x + threadIdx.x;
    if (i < b) { g_maxenc[i] = 0u; g_sum[i] = 0.0f; }
}
__global__ void k_dummy() { if (threadIdx.x == 0) g_dummy = 1; }

// ---------------------------------------------------------------------------
__global__ void k_graph(const float* __restrict__ gf,
                        const float* __restrict__ W1,
                        const float* __restrict__ b1, int b) {
    int warp = (blockIdx.x * blockDim.x + threadIdx.x) >> 5;
    int lane = threadIdx.x & 31;
    if (warp >= b) return;

    const float* row = gf + (size_t)warp * GD;
    float r0 = row[lane];
    float r1 = row[32 + lane];
    float r2 = row[64 + lane];
    float r3 = (lane < (GD - 96)) ? row[96 + lane] : 0.0f;

    float acc = b1[lane];
#pragma unroll
    for (int d = 0; d < GD; d++) {
        float v;
        if      (d < 32) v = __shfl_sync(0xFFFFFFFFu, r0, d);
        else if (d < 64) v = __shfl_sync(0xFFFFFFFFu, r1, d - 32);
        else if (d < 96) v = __shfl_sync(0xFFFFFFFFu, r2, d - 64);
        else             v = __shfl_sync(0xFFFFFFFFu, r3, d - 96);
        acc = fmaf(v, W1[(NEU + d) * HID + lane], acc);
    }
    g_G[warp * HID + lane] = acc;
}

// ---------------------------------------------------------------------------
// k_logits v9: persistent warps + cp.async double-buffered raw staging +
// in-register bf16-split fragments (no bf16 smem, no ldmatrix for A).
//   raw tile: [node][16 float4], chunk m stored at column m ^ (node&15)
//   per warp: two 8 KB raw buffers; W fragments built once from scratch area
// ---------------------------------------------------------------------------
#define STRB    144
#define WARPBUF 16384                    // 2 x 8192 raw buffers
#define OFF_W2  65536
#define OFF_B2  65664
#define SMEMSZ  65792

__global__ void __launch_bounds__(128)
k_logits(const float* __restrict__ x,
         const int* __restrict__ nb,
         const float* __restrict__ W1,
         const float* __restrict__ W2,
         const float* __restrict__ b2, int n) {
    extern __shared__ __align__(128) char smem[];
    uint32_t sb = smem_u32(smem);
    int tid = threadIdx.x;
    int w   = tid >> 5;
    int l   = tid & 31;

    // ---- setup: W1[0:64] -> Wh/Wl scratch tiles at smem[0 / 4608] ----
    for (int t = tid; t < NEU * HID; t += 128) {
        int k = t >> 5, h = t & 31;          // W1[k][h]
        float wv = W1[t];
        __nv_bfloat16 wh = __float2bfloat16(wv);
        float wl = wv - __bfloat162float(wh);
        ((__nv_bfloat16*)(smem))[h * 72 + k]        = wh;
        ((__nv_bfloat16*)(smem + 4608))[h * 72 + k] = __float2bfloat16(wl);
    }
    if (tid < HID) ((float*)(smem + OFF_W2))[tid] = W2[tid];
    if (tid == 0)  ((float*)(smem + OFF_B2))[0]   = b2[0];
    __syncthreads();

    int g = l >> 2, t4 = l & 3;

    float2 w2p[4];
#pragma unroll
    for (int n8 = 0; n8 < 4; n8++)
        w2p[n8] = *(const float2*)(smem + OFF_W2 + (n8 * 8 + 2 * t4) * 4);
    float b2v = ((const float*)(smem + OFF_B2))[0];

    uint32_t Bh[4][4][2], Bl[4][4][2];
#pragma unroll
    for (int n8 = 0; n8 < 4; n8++)
#pragma unroll
        for (int kg = 0; kg < 4; kg++) {
            uint32_t ba = sb + (n8 * 8 + (l & 7)) * STRB
                        + ((l >> 3) & 1) * 16 + kg * 32;
            ldsm_x2(Bh[n8][kg], ba);
            ldsm_x2(Bl[n8][kg], ba + 4608);
        }
    __syncthreads();   // scratch (inside warp0's raw region) no longer needed

    const char* wbase = smem + w * WARPBUF;
    uint32_t    wbu32 = sb + w * WARPBUF;

    long ntiles = (n + 31) / 32;
    long wstep  = (long)gridDim.x * 4;
    long tile   = (long)blockIdx.x * 4 + w;
    int  bsel   = 0;

    // prologue: stage first tile into buffer 0
    if (tile < ntiles) {
#pragma unroll
        for (int j = 0; j < 16; j++) {
            int  id = j * 32 + l;
            int  node = id >> 4, m = id & 15;
            long gn = tile * 32 + node;
            if (gn > n - 1) gn = n - 1;
            cp16(wbu32 + node * 256 + ((m ^ (node & 15)) << 4),
                 x + gn * NEU + m * 4);
        }
    }
    CP_COMMIT();

    for (; tile < ntiles; tile += wstep) {
        long node0 = tile * 32;
        long nxt   = tile + wstep;

        // prefetch next tile into the other buffer
        if (nxt < ntiles) {
            uint32_t dst0 = wbu32 + (bsel ^ 1) * 8192;
#pragma unroll
            for (int j = 0; j < 16; j++) {
                int  id = j * 32 + l;
                int  node = id >> 4, m = id & 15;
                long gn = nxt * 32 + node;
                if (gn > n - 1) gn = n - 1;
                cp16(dst0 + node * 256 + ((m ^ (node & 15)) << 4),
                     x + gn * NEU + m * 4);
            }
        }
        CP_COMMIT();
        CP_WAIT1();          // current buffer's group complete
        __syncwarp();

        const char* buf = wbase + bsel * 8192;

#pragma unroll
        for (int si = 0; si < 2; si++) {
            float acc[4][4];
#pragma unroll
            for (int n8 = 0; n8 < 4; n8++)
#pragma unroll
                for (int c = 0; c < 4; c++) acc[n8][c] = 0.0f;

#pragma unroll
            for (int kg = 0; kg < 4; kg++) {
                uint32_t ah[4], al[4];
                int colb = kg * 16 + 2 * t4;
#pragma unroll
                for (int r2 = 0; r2 < 2; r2++) {
                    int node = si * 16 + g + r2 * 8;
                    const char* rowp = buf + node * 256;
                    int n15 = node & 15;
#pragma unroll
                    for (int c2 = 0; c2 < 2; c2++) {
                        int col = colb + c2 * 8;
                        int f4  = col >> 2;
                        float2 f = *(const float2*)(rowp + ((f4 ^ n15) << 4)
                                                    + (col & 3) * 4);
                        __nv_bfloat162 hi = __floats2bfloat162_rn(f.x, f.y);
                        float rx = f.x - __bfloat162float(hi.x);
                        float ry = f.y - __bfloat162float(hi.y);
                        __nv_bfloat162 lo = __floats2bfloat162_rn(rx, ry);
                        ah[c2 * 2 + r2] = *(const uint32_t*)&hi;
                        al[c2 * 2 + r2] = *(const uint32_t*)&lo;
                    }
                }
#pragma unroll
                for (int n8 = 0; n8 < 4; n8++) {
                    mma_bf16(acc[n8], ah, Bh[n8][kg]);
                    mma_bf16(acc[n8], al, Bh[n8][kg]);
                    mma_bf16(acc[n8], ah, Bl[n8][kg]);
                }
            }

            // ---- epilogue: rows g and g+8 of this subtile ----
            long giA = node0 + si * 16 + g;
            long giB = giA + 8;
            bool vA = (giA < n), vB = (giB < n);
            int  segA = nb[vA ? giA : (n - 1)];
            int  segB = nb[vB ? giB : (n - 1)];

            float pA = 0.0f, pB = 0.0f;
#pragma unroll
            for (int n8 = 0; n8 < 4; n8++) {
                float2 ga = *(const float2*)(g_G + (size_t)segA * HID + n8 * 8 + 2 * t4);
                float2 gb = *(const float2*)(g_G + (size_t)segB * HID + n8 * 8 + 2 * t4);
                float a0 = acc[n8][0] + ga.x;
                float a1 = acc[n8][1] + ga.y;
                float a2 = acc[n8][2] + gb.x;
                float a3 = acc[n8][3] + gb.y;
                float s0 = (a0 > 20.0f) ? a0 : __logf(1.0f + __expf(a0));
                float s1 = (a1 > 20.0f) ? a1 : __logf(1.0f + __expf(a1));
                float s2 = (a2 > 20.0f) ? a2 : __logf(1.0f + __expf(a2));
                float s3 = (a3 > 20.0f) ? a3 : __logf(1.0f + __expf(a3));
                pA = fmaf(s0, w2p[n8].x, pA);
                pA = fmaf(s1, w2p[n8].y, pA);
                pB = fmaf(s2, w2p[n8].x, pB);
                pB = fmaf(s3, w2p[n8].y, pB);
            }
            pA += __shfl_xor_sync(0xFFFFFFFFu, pA, 1);
            pA += __shfl_xor_sync(0xFFFFFFFFu, pA, 2);
            pB += __shfl_xor_sync(0xFFFFFFFFu, pB, 1);
            pB += __shfl_xor_sync(0xFFFFFFFFu, pB, 2);
            float lgA = pA + b2v;
            float lgB = pB + b2v;

            if (t4 == 0) {
                if (vA) g_logit[giA] = lgA;
                if (vB) g_logit[giB] = lgB;
                if (vA && vB && segA == segB) {
                    atomicMax(&g_maxenc[segA], enc_f(fmaxf(lgA, lgB)));
                } else {
                    if (vA) atomicMax(&g_maxenc[segA], enc_f(lgA));
                    if (vB) atomicMax(&g_maxenc[segB], enc_f(lgB));
                }
            }
        }
        __syncwarp();       // protect raw buffer before next-iteration stage
        bsel ^= 1;
    }
}

// ---------------------------------------------------------------------------
__global__ void __launch_bounds__(256)
k_exp(const int* __restrict__ nb, int n) {
    int i = blockIdx.x * blockDim.x + threadIdx.x;
    int lane = threadIdx.x & 31;

    int   seg = -1;
    float e   = 0.0f;
    if (i < n) {
        seg = nb[i];
        float mx = dec_f(g_maxenc[seg]);
        e = __expf(g_logit[i] - mx);
    }
#pragma unroll
    for (int off = 1; off < 32; off <<= 1) {
        int   os = __shfl_down_sync(0xFFFFFFFFu, seg, off);
        float oe = __shfl_down_sync(0xFFFFFFFFu, e,   off);
        if (lane + off < 32 && os == seg) e += oe;
    }
    int  ps   = __shfl_up_sync(0xFFFFFFFFu, seg, 1);
    bool head = (lane == 0) || (ps != seg);
    if (head && seg >= 0) atomicAdd(&g_sum[seg], e);
}

// ---------------------------------------------------------------------------
__global__ void __launch_bounds__(256)
k_div(const int* __restrict__ nb, float* __restrict__ out, int n) {
    int i = blockIdx.x * blockDim.x + threadIdx.x;
    if (i < n) {
        int   seg = nb[i];
        float mx  = dec_f(g_maxenc[seg]);
        float e   = __expf(g_logit[i] - mx);
        out[i] = e / g_sum[seg];
    }
}

// ---------------------------------------------------------------------------
extern "C" void kernel_launch(void* const* d_in, const int* in_sizes, int n_in,
                              void* d_out, int out_size) {
    const float* x   = (const float*)d_in[0];
    const int*   nb  = (const int*)d_in[1];
    const float* gf  = (const float*)d_in[2];
    const float* W1  = (const float*)d_in[3];
    const float* b1  = (const float*)d_in[4];
    const float* W2  = (const float*)d_in[5];
    const float* b2  = (const float*)d_in[6];
    float*       out = (float*)d_out;

    int n = in_sizes[0] / NEU;   // nodes
    int b = in_sizes[2] / GD;    // graphs

    cudaFuncSetAttribute(k_logits, cudaFuncAttributeMaxDynamicSharedMemorySize,
                         SMEMSZ);

    k_init<<<(b + 255) / 256, 256>>>(b);
    k_graph<<<(b + 7) / 8, 256>>>(gf, W1, b1, b);
    k_dummy<<<1, 32>>>();                       // position k_logits for ncu -s 5

    k_logits<<<444, 128, SMEMSZ>>>(x, nb, W1, W2, b2, n);

    int blocks = (n + 255) / 256;
    k_exp<<<blocks, 256>>>(nb, n);
    k_div<<<blocks, 256>>>(nb, out, n);
}

// round 12
// speedup vs baseline: 1.1724x; 1.1724x over previous
#include <cuda_runtime.h>
#include <cuda_bf16.h>
#include <cstdint>

#define NEU   64
#define HID   32
#define GD    103
#define N_MAX 2000128
#define B_MAX 8192

typedef unsigned long long ull;

// Scratch
__device__ float        g_logit[N_MAX];
__device__ float        g_G[B_MAX * HID];
__device__ unsigned int g_maxenc[B_MAX];
__device__ float        g_sum[B_MAX];
__device__ int          g_dummy;

__device__ __forceinline__ unsigned int enc_f(float f) {
    unsigned int u = __float_as_uint(f);
    return (u & 0x80000000u) ? ~u : (u | 0x80000000u);
}
__device__ __forceinline__ float dec_f(unsigned int u) {
    u = (u & 0x80000000u) ? (u & 0x7FFFFFFFu) : ~u;
    return __uint_as_float(u);
}

__device__ __forceinline__ uint32_t smem_u32(const void* p) {
    uint32_t a;
    asm("{ .reg .u64 t; cvta.to.shared.u64 t, %1; cvt.u32.u64 %0, t; }"
        : "=r"(a) : "l"(p));
    return a;
}
__device__ __forceinline__ void ldsm_x2(uint32_t r[2], uint32_t addr) {
    asm volatile("ldmatrix.sync.aligned.m8n8.x2.shared.b16 {%0,%1}, [%2];"
        : "=r"(r[0]), "=r"(r[1]) : "r"(addr));
}
__device__ __forceinline__ void mma_bf16(float c[4], const uint32_t a[4],
                                         const uint32_t b[2]) {
    asm volatile(
        "mma.sync.aligned.m16n8k16.row.col.f32.bf16.bf16.f32 "
        "{%0,%1,%2,%3}, {%4,%5,%6,%7}, {%8,%9}, {%0,%1,%2,%3};"
        : "+f"(c[0]), "+f"(c[1]), "+f"(c[2]), "+f"(c[3])
        : "r"(a[0]), "r"(a[1]), "r"(a[2]), "r"(a[3]), "r"(b[0]), "r"(b[1]));
}
__device__ __forceinline__ void cp16(uint32_t dst, const void* src) {
    asm volatile("cp.async.ca.shared.global [%0], [%1], 16;"
                 :: "r"(dst), "l"(src) : "memory");
}
#define CP_COMMIT() asm volatile("cp.async.commit_group;" ::: "memory")
#define CP_WAIT1()  asm volatile("cp.async.wait_group 1;" ::: "memory")

// ---------------------------------------------------------------------------
__global__ void k_init(int b) {
    int i = blockIdx.x * blockDim.x + threadIdx.x;
    if (i < b) { g_maxenc[i] = 0u; g_sum[i] = 0.0f; }
}
__global__ void k_dummy() { if (threadIdx.x == 0) g_dummy = 1; }

// ---------------------------------------------------------------------------
__global__ void k_graph(const float* __restrict__ gf,
                        const float* __restrict__ W1,
                        const float* __restrict__ b1, int b) {
    int warp = (blockIdx.x * blockDim.x + threadIdx.x) >> 5;
    int lane = threadIdx.x & 31;
    if (warp >= b) return;

    const float* row = gf + (size_t)warp * GD;
    float r0 = row[lane];
    float r1 = row[32 + lane];
    float r2 = row[64 + lane];
    float r3 = (lane < (GD - 96)) ? row[96 + lane] : 0.0f;

    float acc = b1[lane];
#pragma unroll
    for (int d = 0; d < GD; d++) {
        float v;
        if      (d < 32) v = __shfl_sync(0xFFFFFFFFu, r0, d);
        else if (d < 64) v = __shfl_sync(0xFFFFFFFFu, r1, d - 32);
        else if (d < 96) v = __shfl_sync(0xFFFFFFFFu, r2, d - 64);
        else             v = __shfl_sync(0xFFFFFFFFu, r3, d - 96);
        acc = fmaf(v, W1[(NEU + d) * HID + lane], acc);
    }
    g_G[warp * HID + lane] = acc;
}

// ---------------------------------------------------------------------------
// k_logits v10: occupancy-first.
//   16-node warp tiles, 2x4KB double buffers (32KB), Bh in regs,
//   Bl via ldmatrix from persistent 4.6KB Wl tile, launch_bounds(128,5).
// ---------------------------------------------------------------------------
#define STRB    144
#define WARPBUF 8192                     // 2 x 4096 raw buffers per warp
#define OFF_WL  32768                    // persistent Wl tile (4608 B)
#define OFF_W2  37376
#define OFF_B2  37504
#define SMEMSZ  37632

__global__ void __launch_bounds__(128, 5)
k_logits(const float* __restrict__ x,
         const int* __restrict__ nb,
         const float* __restrict__ W1,
         const float* __restrict__ W2,
         const float* __restrict__ b2, int n) {
    extern __shared__ __align__(128) char smem[];
    uint32_t sb = smem_u32(smem);
    int tid = threadIdx.x;
    int w   = tid >> 5;
    int l   = tid & 31;

    // ---- setup: Wh scratch at smem[0..4608) (inside warp buffers, temp);
    //      Wl persistent at OFF_WL ----
    for (int t = tid; t < NEU * HID; t += 128) {
        int k = t >> 5, h = t & 31;          // W1[k][h]
        float wv = W1[t];
        __nv_bfloat16 wh = __float2bfloat16(wv);
        float wl = wv - __bfloat162float(wh);
        ((__nv_bfloat16*)(smem))[h * 72 + k]          = wh;
        ((__nv_bfloat16*)(smem + OFF_WL))[h * 72 + k] = __float2bfloat16(wl);
    }
    if (tid < HID) ((float*)(smem + OFF_W2))[tid] = W2[tid];
    if (tid == 0)  ((float*)(smem + OFF_B2))[0]   = b2[0];
    __syncthreads();

    int g = l >> 2, t4 = l & 3;

    float2 w2p[4];
#pragma unroll
    for (int n8 = 0; n8 < 4; n8++)
        w2p[n8] = *(const float2*)(smem + OFF_W2 + (n8 * 8 + 2 * t4) * 4);
    float b2v = ((const float*)(smem + OFF_B2))[0];

    // Bh fragments in registers; Bl stays in smem (ldmatrix per tile)
    uint32_t Bh[4][4][2];
    uint32_t blbase = sb + OFF_WL + (l & 7) * STRB + ((l >> 3) & 1) * 16;
#pragma unroll
    for (int n8 = 0; n8 < 4; n8++)
#pragma unroll
        for (int kg = 0; kg < 4; kg++) {
            uint32_t ba = sb + (n8 * 8 + (l & 7)) * STRB
                        + ((l >> 3) & 1) * 16 + kg * 32;
            ldsm_x2(Bh[n8][kg], ba);
        }
    __syncthreads();   // Wh scratch (warp0/1 buffer region) no longer needed

    const char* wbase = smem + w * WARPBUF;
    uint32_t    wbu32 = sb + w * WARPBUF;

    long ntiles = (n + 15) / 16;            // 16-node tiles
    long wstep  = (long)gridDim.x * 4;
    long tile   = (long)blockIdx.x * 4 + w;
    int  bsel   = 0;

    // prologue: stage first tile into buffer 0 (8 cp16 per lane)
    if (tile < ntiles) {
#pragma unroll
        for (int j = 0; j < 8; j++) {
            int  id = j * 32 + l;
            int  node = id >> 4, m = id & 15;
            long gn = tile * 16 + node;
            if (gn > n - 1) gn = n - 1;
            cp16(wbu32 + node * 256 + ((m ^ node) << 4),
                 x + gn * NEU + m * 4);
        }
    }
    CP_COMMIT();

    for (; tile < ntiles; tile += wstep) {
        long node0 = tile * 16;
        long nxt   = tile + wstep;

        if (nxt < ntiles) {
            uint32_t dst0 = wbu32 + (bsel ^ 1) * 4096;
#pragma unroll
            for (int j = 0; j < 8; j++) {
                int  id = j * 32 + l;
                int  node = id >> 4, m = id & 15;
                long gn = nxt * 16 + node;
                if (gn > n - 1) gn = n - 1;
                cp16(dst0 + node * 256 + ((m ^ node) << 4),
                     x + gn * NEU + m * 4);
            }
        }
        CP_COMMIT();
        CP_WAIT1();
        __syncwarp();

        const char* buf = wbase + bsel * 4096;

        float acc[4][4];
#pragma unroll
        for (int n8 = 0; n8 < 4; n8++)
#pragma unroll
            for (int c = 0; c < 4; c++) acc[n8][c] = 0.0f;

#pragma unroll
        for (int kg = 0; kg < 4; kg++) {
            uint32_t ah[4], al[4];
            int colb = kg * 16 + 2 * t4;
#pragma unroll
            for (int r2 = 0; r2 < 2; r2++) {
                int node = g + r2 * 8;
                const char* rowp = buf + node * 256;
#pragma unroll
                for (int c2 = 0; c2 < 2; c2++) {
                    int col = colb + c2 * 8;
                    int f4  = col >> 2;
                    float2 f = *(const float2*)(rowp + ((f4 ^ node) << 4)
                                                + (col & 3) * 4);
                    __nv_bfloat162 hi = __floats2bfloat162_rn(f.x, f.y);
                    float rx = f.x - __bfloat162float(hi.x);
                    float ry = f.y - __bfloat162float(hi.y);
                    __nv_bfloat162 lo = __floats2bfloat162_rn(rx, ry);
                    ah[c2 * 2 + r2] = *(const uint32_t*)&hi;
                    al[c2 * 2 + r2] = *(const uint32_t*)&lo;
                }
            }
#pragma unroll
            for (int n8 = 0; n8 < 4; n8++) {
                uint32_t Bl[2];
                ldsm_x2(Bl, blbase + n8 * 8 * STRB + kg * 32);
                mma_bf16(acc[n8], ah, Bh[n8][kg]);
                mma_bf16(acc[n8], al, Bh[n8][kg]);
                mma_bf16(acc[n8], ah, Bl);
            }
        }

        // ---- epilogue: rows g and g+8 ----
        long giA = node0 + g;
        long giB = giA + 8;
        bool vA = (giA < n), vB = (giB < n);
        int  segA = nb[vA ? giA : (n - 1)];
        int  segB = nb[vB ? giB : (n - 1)];

        float pA = 0.0f, pB = 0.0f;
#pragma unroll
        for (int n8 = 0; n8 < 4; n8++) {
            float2 ga = *(const float2*)(g_G + (size_t)segA * HID + n8 * 8 + 2 * t4);
            float2 gb = *(const float2*)(g_G + (size_t)segB * HID + n8 * 8 + 2 * t4);
            float a0 = acc[n8][0] + ga.x;
            float a1 = acc[n8][1] + ga.y;
            float a2 = acc[n8][2] + gb.x;
            float a3 = acc[n8][3] + gb.y;
            float s0 = (a0 > 20.0f) ? a0 : __logf(1.0f + __expf(a0));
            float s1 = (a1 > 20.0f) ? a1 : __logf(1.0f + __expf(a1));
            float s2 = (a2 > 20.0f) ? a2 : __logf(1.0f + __expf(a2));
            float s3 = (a3 > 20.0f) ? a3 : __logf(1.0f + __expf(a3));
            pA = fmaf(s0, w2p[n8].x, pA);
            pA = fmaf(s1, w2p[n8].y, pA);
            pB = fmaf(s2, w2p[n8].x, pB);
            pB = fmaf(s3, w2p[n8].y, pB);
        }
        pA += __shfl_xor_sync(0xFFFFFFFFu, pA, 1);
        pA += __shfl_xor_sync(0xFFFFFFFFu, pA, 2);
        pB += __shfl_xor_sync(0xFFFFFFFFu, pB, 1);
        pB += __shfl_xor_sync(0xFFFFFFFFu, pB, 2);
        float lgA = pA + b2v;
        float lgB = pB + b2v;

        if (t4 == 0) {
            if (vA) g_logit[giA] = lgA;
            if (vB) g_logit[giB] = lgB;
            if (vA && vB && segA == segB) {
                atomicMax(&g_maxenc[segA], enc_f(fmaxf(lgA, lgB)));
            } else {
                if (vA) atomicMax(&g_maxenc[segA], enc_f(lgA));
                if (vB) atomicMax(&g_maxenc[segB], enc_f(lgB));
            }
        }
        __syncwarp();
        bsel ^= 1;
    }
}

// ---------------------------------------------------------------------------
__global__ void __launch_bounds__(256)
k_exp(const int* __restrict__ nb, int n) {
    int i = blockIdx.x * blockDim.x + threadIdx.x;
    int lane = threadIdx.x & 31;

    int   seg = -1;
    float e   = 0.0f;
    if (i < n) {
        seg = nb[i];
        float mx = dec_f(g_maxenc[seg]);
        e = __expf(g_logit[i] - mx);
    }
#pragma unroll
    for (int off = 1; off < 32; off <<= 1) {
        int   os = __shfl_down_sync(0xFFFFFFFFu, seg, off);
        float oe = __shfl_down_sync(0xFFFFFFFFu, e,   off);
        if (lane + off < 32 && os == seg) e += oe;
    }
    int  ps   = __shfl_up_sync(0xFFFFFFFFu, seg, 1);
    bool head = (lane == 0) || (ps != seg);
    if (head && seg >= 0) atomicAdd(&g_sum[seg], e);
}

// ---------------------------------------------------------------------------
__global__ void __launch_bounds__(256)
k_div(const int* __restrict__ nb, float* __restrict__ out, int n) {
    int i = blockIdx.x * blockDim.x + threadIdx.x;
    if (i < n) {
        int   seg = nb[i];
        float mx  = dec_f(g_maxenc[seg]);
        float e   = __expf(g_logit[i] - mx);
        out[i] = e / g_sum[seg];
    }
}

// ---------------------------------------------------------------------------
extern "C" void kernel_launch(void* const* d_in, const int* in_sizes, int n_in,
                              void* d_out, int out_size) {
    const float* x   = (const float*)d_in[0];
    const int*   nb  = (const int*)d_in[1];
    const float* gf  = (const float*)d_in[2];
    const float* W1  = (const float*)d_in[3];
    const float* b1  = (const float*)d_in[4];
    const float* W2  = (const float*)d_in[5];
    const float* b2  = (const float*)d_in[6];
    float*       out = (float*)d_out;

    int n = in_sizes[0] / NEU;   // nodes
    int b = in_sizes[2] / GD;    // graphs

    cudaFuncSetAttribute(k_logits, cudaFuncAttributeMaxDynamicSharedMemorySize,
                         SMEMSZ);

    k_init<<<(b + 255) / 256, 256>>>(b);
    k_graph<<<(b + 7) / 8, 256>>>(gf, W1, b1, b);
    k_dummy<<<1, 32>>>();                       // position k_logits for ncu -s 5

    k_logits<<<740, 128, SMEMSZ>>>(x, nb, W1, W2, b2, n);

    int blocks = (n + 255) / 256;
    k_exp<<<blocks, 256>>>(nb, n);
    k_div<<<blocks, 256>>>(nb, out, n);
}